// round 1
// baseline (speedup 1.0000x reference)
#include <cuda_runtime.h>
#include <cstdint>

// Problem constants
constexpr int Bb  = 2;
constexpr int NC  = 256;
constexpr int CN  = 256;
constexpr int K   = 16;
constexpr int DN  = 64;
constexpr int HM  = 128;   // hidden (msg == state)
constexpr int F   = 192;   // 3*DN
constexpr int HMOD = 64;
constexpr int MOD_OUT = 5;

constexpr int AP = 260;    // A-tile pitch in floats (padded; 260*4B is 16B-multiple)

// Scratch (static device globals; no runtime allocation)
__device__ float g_agg[(size_t)Bb * NC * CN * DN];   //  33.5 MB
__device__ float g_mh [(size_t)Bb * NC * CN * HM];   //  67.1 MB

__device__ __forceinline__ float gelu_f(float x) {
    // JAX default gelu (tanh approximation)
    float x3 = x * x * x;
    return 0.5f * x * (1.0f + tanhf(0.7978845608028654f * (x + 0.044715f * x3)));
}

// ---------------------------------------------------------------------------
// Kernel 1: connection-weighted aggregation.
// One block per (b,n). h tile [256][64] in shared; gather via conn_idx.
// ---------------------------------------------------------------------------
__global__ __launch_bounds__(256) void agg_kernel(
    const float* __restrict__ h,
    const float* __restrict__ w_conn,
    const int*   __restrict__ conn)
{
    extern __shared__ float smf[];
    float4* h_sm = reinterpret_cast<float4*>(smf);   // [256][16] float4

    int bn = blockIdx.x;
    int n  = bn & (NC - 1);

    const float4* hg = reinterpret_cast<const float4*>(h) + (size_t)bn * CN * DN / 4;
    for (int i = threadIdx.x; i < CN * DN / 4; i += 256) h_sm[i] = hg[i];
    __syncthreads();

    int dq = threadIdx.x & 3;     // quarter of d-range (16 floats)
    int cr = threadIdx.x >> 2;    // 0..63

    for (int cp = 0; cp < 4; cp++) {
        int c = cp * 64 + cr;
        float4 a0 = {0,0,0,0}, a1 = {0,0,0,0}, a2 = {0,0,0,0}, a3 = {0,0,0,0};
        const int*   ci = conn   + ((size_t)n  * CN + c) * K;
        const float* wc = w_conn + ((size_t)bn * CN + c) * K;
        #pragma unroll
        for (int k = 0; k < K; k++) {
            int   idx = ci[k];
            float w   = wc[k];
            const float4* row = h_sm + idx * (DN / 4) + dq * 4;
            float4 r0 = row[0], r1 = row[1], r2 = row[2], r3 = row[3];
            a0.x += w * r0.x; a0.y += w * r0.y; a0.z += w * r0.z; a0.w += w * r0.w;
            a1.x += w * r1.x; a1.y += w * r1.y; a1.z += w * r1.z; a1.w += w * r1.w;
            a2.x += w * r2.x; a2.y += w * r2.y; a2.z += w * r2.z; a2.w += w * r2.w;
            a3.x += w * r3.x; a3.y += w * r3.y; a3.z += w * r3.z; a3.w += w * r3.w;
        }
        float4* out = reinterpret_cast<float4*>(g_agg + ((size_t)bn * CN + c) * DN) + dq * 4;
        out[0] = a0; out[1] = a1; out[2] = a2; out[3] = a3;
    }
}

// ---------------------------------------------------------------------------
// Kernel 2/4: grouped MLP layer 1 (feat[256][192] @ W1[128][192]^T, gelu).
// MODE 0: feat = [h | agg | neuron_id]   (msg MLP)
// MODE 1: feat = [h | msg | ctx-bcast]   (state MLP)
// One block per (b,n), 512 threads, 8c x 8j register microtile.
// Writes gelu'd hidden to g_mh.
// ---------------------------------------------------------------------------
template<int MODE>
__global__ __launch_bounds__(512, 1) void mlp1_kernel(
    const float* __restrict__ h,
    const float* __restrict__ s1,     // MODE 1: msg (from d_out); MODE 0: unused (uses g_agg)
    const float* __restrict__ s2,     // MODE 0: neuron_id; MODE 1: cell_context
    const float* __restrict__ w1,     // [G][HM][F]
    const float* __restrict__ b1,     // [G][HM]
    const int*   __restrict__ c2g)
{
    extern __shared__ float sm[];
    float* A  = sm;                 // [16][AP]
    float* W  = sm + 16 * AP;       // [HM*F]
    float* Bs = W + HM * F;         // [HM]

    int bn  = blockIdx.x;
    int n   = bn & (NC - 1);
    int g   = c2g[n];
    int tid = threadIdx.x;

    // Stage W1[g], b1[g]
    {
        const float4* wsrc = reinterpret_cast<const float4*>(w1 + (size_t)g * HM * F);
        float4*       wdst = reinterpret_cast<float4*>(W);
        for (int i = tid; i < HM * F / 4; i += 512) wdst[i] = wsrc[i];
        if (tid < HM) Bs[tid] = b1[g * HM + tid];
    }

    int tc = tid & 31, tj = tid >> 5;
    int c0 = tc * 8,   j0 = tj * 8;

    float acc[8][8];
    #pragma unroll
    for (int i = 0; i < 8; i++)
        #pragma unroll
        for (int j = 0; j < 8; j++) acc[i][j] = 0.0f;

    int fq   = tid & 3;     // f quarter within 16-wide tile
    int crow = tid >> 2;    // 0..127

    const float* base_h = h + (size_t)bn * CN * DN;
    const float* base1  = (MODE == 0) ? (g_agg + (size_t)bn * CN * DN)
                                      : (s1    + (size_t)bn * CN * DN);
    const float* base2  = (MODE == 0) ? (s2 + (size_t)n * CN * DN)   // neuron_id rows
                                      : (s2 + (size_t)bn * DN);      // ctx broadcast

    for (int t = 0; t < 12; t++) {
        __syncthreads();
        int fo = (t & 3) * 16;
        const float* src = (t < 4) ? base_h : ((t < 8) ? base1 : base2);
        #pragma unroll
        for (int cp = 0; cp < 2; cp++) {
            int c = cp * 128 + crow;
            float4 v;
            if (MODE == 1 && t >= 8)
                v = *reinterpret_cast<const float4*>(base2 + fo + fq * 4);   // broadcast row
            else
                v = *reinterpret_cast<const float4*>(src + (size_t)c * DN + fo + fq * 4);
            int kb = fq * 4;
            A[(kb + 0) * AP + c] = v.x;
            A[(kb + 1) * AP + c] = v.y;
            A[(kb + 2) * AP + c] = v.z;
            A[(kb + 3) * AP + c] = v.w;
        }
        __syncthreads();

        int k0 = t * 16;
        #pragma unroll 4
        for (int kk = 0; kk < 16; kk++) {
            const float4* ap = reinterpret_cast<const float4*>(A + kk * AP + c0);
            float4 av0 = ap[0], av1 = ap[1];
            float a[8] = {av0.x, av0.y, av0.z, av0.w, av1.x, av1.y, av1.z, av1.w};
            #pragma unroll
            for (int jj = 0; jj < 8; jj++) {
                float bv = W[(j0 + jj) * F + k0 + kk];
                #pragma unroll
                for (int cc = 0; cc < 8; cc++)
                    acc[cc][jj] = fmaf(a[cc], bv, acc[cc][jj]);
            }
        }
    }

    // Epilogue: + bias, gelu, store hidden to g_mh [bn][c][j]
    float bb[8];
    #pragma unroll
    for (int jj = 0; jj < 8; jj++) bb[jj] = Bs[j0 + jj];

    #pragma unroll
    for (int cc = 0; cc < 8; cc++) {
        float* op = g_mh + ((size_t)bn * CN + (c0 + cc)) * HM + j0;
        float4 v0, v1;
        v0.x = gelu_f(acc[cc][0] + bb[0]);
        v0.y = gelu_f(acc[cc][1] + bb[1]);
        v0.z = gelu_f(acc[cc][2] + bb[2]);
        v0.w = gelu_f(acc[cc][3] + bb[3]);
        v1.x = gelu_f(acc[cc][4] + bb[4]);
        v1.y = gelu_f(acc[cc][5] + bb[5]);
        v1.z = gelu_f(acc[cc][6] + bb[6]);
        v1.w = gelu_f(acc[cc][7] + bb[7]);
        *reinterpret_cast<float4*>(op)     = v0;
        *reinterpret_cast<float4*>(op + 4) = v1;
    }
}

// ---------------------------------------------------------------------------
// Kernel 3/5: grouped MLP layer 2 (mh[256][128] @ W2[64][128]^T + bias).
// MODE 0: out = msg region.  MODE 1: out = h + result (residual) -> h_new.
// One block per (b,n), 256 threads, 8c x 8j microtile over 256x64 output.
// ---------------------------------------------------------------------------
template<int MODE>
__global__ __launch_bounds__(256) void mlp2_kernel(
    const float* __restrict__ w2,     // [G][DN][HM]
    const float* __restrict__ b2,     // [G][DN]
    const int*   __restrict__ c2g,
    const float* __restrict__ h,      // residual source (MODE 1)
    float*       __restrict__ out)
{
    extern __shared__ float sm[];
    float* A  = sm;                  // [16][AP]
    float* W  = sm + 16 * AP;        // [DN*HM]
    float* Bs = W + DN * HM;         // [DN]

    int bn  = blockIdx.x;
    int n   = bn & (NC - 1);
    int g   = c2g[n];
    int tid = threadIdx.x;

    {
        const float4* wsrc = reinterpret_cast<const float4*>(w2 + (size_t)g * DN * HM);
        float4*       wdst = reinterpret_cast<float4*>(W);
        for (int i = tid; i < DN * HM / 4; i += 256) wdst[i] = wsrc[i];
        if (tid < DN) Bs[tid] = b2[g * DN + tid];
    }

    int tc = tid & 31, tj = tid >> 5;     // 8 warps -> j0 in [0,64)
    int c0 = tc * 8,   j0 = tj * 8;

    float acc[8][8];
    #pragma unroll
    for (int i = 0; i < 8; i++)
        #pragma unroll
        for (int j = 0; j < 8; j++) acc[i][j] = 0.0f;

    int fq   = tid & 3;
    int crow = tid >> 2;                  // 0..63
    const float* mh = g_mh + (size_t)bn * CN * HM;

    for (int t = 0; t < 8; t++) {
        __syncthreads();
        int k0 = t * 16;
        #pragma unroll
        for (int cp = 0; cp < 4; cp++) {
            int c = cp * 64 + crow;
            float4 v = *reinterpret_cast<const float4*>(mh + (size_t)c * HM + k0 + fq * 4);
            int kb = fq * 4;
            A[(kb + 0) * AP + c] = v.x;
            A[(kb + 1) * AP + c] = v.y;
            A[(kb + 2) * AP + c] = v.z;
            A[(kb + 3) * AP + c] = v.w;
        }
        __syncthreads();

        #pragma unroll 4
        for (int kk = 0; kk < 16; kk++) {
            const float4* ap = reinterpret_cast<const float4*>(A + kk * AP + c0);
            float4 av0 = ap[0], av1 = ap[1];
            float a[8] = {av0.x, av0.y, av0.z, av0.w, av1.x, av1.y, av1.z, av1.w};
            #pragma unroll
            for (int jj = 0; jj < 8; jj++) {
                float bv = W[(j0 + jj) * HM + k0 + kk];
                #pragma unroll
                for (int cc = 0; cc < 8; cc++)
                    acc[cc][jj] = fmaf(a[cc], bv, acc[cc][jj]);
            }
        }
    }

    float bb[8];
    #pragma unroll
    for (int jj = 0; jj < 8; jj++) bb[jj] = Bs[j0 + jj];

    #pragma unroll
    for (int cc = 0; cc < 8; cc++) {
        int c = c0 + cc;
        float4 v0, v1;
        v0.x = acc[cc][0] + bb[0]; v0.y = acc[cc][1] + bb[1];
        v0.z = acc[cc][2] + bb[2]; v0.w = acc[cc][3] + bb[3];
        v1.x = acc[cc][4] + bb[4]; v1.y = acc[cc][5] + bb[5];
        v1.z = acc[cc][6] + bb[6]; v1.w = acc[cc][7] + bb[7];
        if (MODE == 1) {
            const float4* hp = reinterpret_cast<const float4*>(
                h + ((size_t)bn * CN + c) * DN + j0);
            float4 h0 = hp[0], h1 = hp[1];
            v0.x += h0.x; v0.y += h0.y; v0.z += h0.z; v0.w += h0.w;
            v1.x += h1.x; v1.y += h1.y; v1.z += h1.z; v1.w += h1.w;
        }
        float* op = out + ((size_t)bn * CN + c) * DN + j0;
        *reinterpret_cast<float4*>(op)     = v0;
        *reinterpret_cast<float4*>(op + 4) = v1;
    }
}

// ---------------------------------------------------------------------------
// Kernel 6: per-cell modulation MLP on pooled means.
// ---------------------------------------------------------------------------
__global__ __launch_bounds__(128) void mod_kernel(
    const float* __restrict__ hnew,
    const float* __restrict__ msg,
    const float* __restrict__ mw1,    // [NC][2DN][HMOD]
    const float* __restrict__ mb1,    // [NC][HMOD]
    const float* __restrict__ mw2,    // [NC][HMOD][MOD_OUT]
    const float* __restrict__ mb2,    // [NC][MOD_OUT]
    float*       __restrict__ mod)
{
    __shared__ float pooled[2 * DN];
    __shared__ float ph[HMOD];

    int bn  = blockIdx.x;
    int n   = bn & (NC - 1);
    int tid = threadIdx.x;

    const float* src = ((tid < DN) ? hnew : msg) + (size_t)bn * CN * DN + (tid & (DN - 1));
    float s = 0.0f;
    #pragma unroll 4
    for (int c = 0; c < CN; c++) s += src[(size_t)c * DN];
    pooled[tid] = s * (1.0f / CN);
    __syncthreads();

    if (tid < HMOD) {
        const float* w = mw1 + (size_t)n * (2 * DN) * HMOD + tid;
        float acc = mb1[n * HMOD + tid];
        #pragma unroll 4
        for (int f = 0; f < 2 * DN; f++) acc = fmaf(pooled[f], w[f * HMOD], acc);
        ph[tid] = gelu_f(acc);
    }
    __syncthreads();

    if (tid < MOD_OUT) {
        const float* w = mw2 + (size_t)n * HMOD * MOD_OUT + tid;
        float acc = mb2[n * MOD_OUT + tid];
        #pragma unroll 4
        for (int k = 0; k < HMOD; k++) acc = fmaf(ph[k], w[k * MOD_OUT], acc);
        mod[bn * MOD_OUT + tid] = acc;
    }
}

// ---------------------------------------------------------------------------
// Launch
// ---------------------------------------------------------------------------
extern "C" void kernel_launch(void* const* d_in, const int* in_sizes, int n_in,
                              void* d_out, int out_size)
{
    const float* h      = (const float*)d_in[0];
    const float* w_conn = (const float*)d_in[1];
    const float* ctx    = (const float*)d_in[2];
    const float* nid    = (const float*)d_in[3];
    const float* mw1    = (const float*)d_in[4];
    const float* mb1    = (const float*)d_in[5];
    const float* mw2    = (const float*)d_in[6];
    const float* mb2    = (const float*)d_in[7];
    const float* sw1    = (const float*)d_in[8];
    const float* sb1    = (const float*)d_in[9];
    const float* sw2    = (const float*)d_in[10];
    const float* sb2    = (const float*)d_in[11];
    const float* modw1  = (const float*)d_in[12];
    const float* modb1  = (const float*)d_in[13];
    const float* modw2  = (const float*)d_in[14];
    const float* modb2  = (const float*)d_in[15];
    const int*   conn   = (const int*)d_in[16];
    const int*   c2g    = (const int*)d_in[17];

    float* out   = (float*)d_out;
    float* o_h   = out;                                      // h_new
    float* o_msg = out + (size_t)Bb * NC * CN * DN;          // msg
    float* o_mod = o_msg + (size_t)Bb * NC * CN * DN;        // mod

    const int grid = Bb * NC;  // 512

    const size_t smA   = (size_t)CN * DN * sizeof(float);                       // 64 KB
    const size_t sm1   = (size_t)(16 * AP + HM * F + HM) * sizeof(float);       // ~115.5 KB
    const size_t sm2   = (size_t)(16 * AP + DN * HM + DN) * sizeof(float);      // ~48.5 KB

    static bool attr_done = false;
    if (!attr_done) {
        cudaFuncSetAttribute(agg_kernel,     cudaFuncAttributeMaxDynamicSharedMemorySize, (int)smA);
        cudaFuncSetAttribute(mlp1_kernel<0>, cudaFuncAttributeMaxDynamicSharedMemorySize, (int)sm1);
        cudaFuncSetAttribute(mlp1_kernel<1>, cudaFuncAttributeMaxDynamicSharedMemorySize, (int)sm1);
        cudaFuncSetAttribute(mlp2_kernel<0>, cudaFuncAttributeMaxDynamicSharedMemorySize, (int)sm2);
        cudaFuncSetAttribute(mlp2_kernel<1>, cudaFuncAttributeMaxDynamicSharedMemorySize, (int)sm2);
        attr_done = true;
    }

    // 1) aggregation
    agg_kernel<<<grid, 256, smA>>>(h, w_conn, conn);
    // 2) msg MLP
    mlp1_kernel<0><<<grid, 512, sm1>>>(h, nullptr, nid, mw1, mb1, c2g);
    mlp2_kernel<0><<<grid, 256, sm2>>>(mw2, mb2, c2g, h, o_msg);
    // 3) state MLP (residual)
    mlp1_kernel<1><<<grid, 512, sm1>>>(h, o_msg, ctx, sw1, sb1, c2g);
    mlp2_kernel<1><<<grid, 256, sm2>>>(sw2, sb2, c2g, h, o_h);
    // 4) modulation MLP
    mod_kernel<<<grid, 128>>>(o_h, o_msg, modw1, modb1, modw2, modb2, o_mod);
}

// round 2
// speedup vs baseline: 1.0750x; 1.0750x over previous
#include <cuda_runtime.h>
#include <cstdint>

// Problem constants
constexpr int Bb  = 2;
constexpr int NC  = 256;
constexpr int CN  = 256;
constexpr int K   = 16;
constexpr int DN  = 64;
constexpr int HM  = 128;   // hidden (msg == state)
constexpr int F   = 192;   // 3*DN
constexpr int HMOD = 64;
constexpr int MOD_OUT = 5;

constexpr int AP = 258;    // A-tile pitch in floats (even -> 8B-aligned rows; 4-way STS conflicts max)

// Scratch (static device globals; no runtime allocation)
__device__ float g_agg[(size_t)Bb * NC * CN * DN];   //  33.5 MB
__device__ float g_mh [(size_t)Bb * NC * CN * HM];   //  67.1 MB

__device__ __forceinline__ float gelu_f(float x) {
    float x3 = x * x * x;
    return 0.5f * x * (1.0f + tanhf(0.7978845608028654f * (x + 0.044715f * x3)));
}

// ---- packed fp32x2 helpers (FFMA2 path, 2x fp32 throughput on sm_103a) ----
__device__ __forceinline__ unsigned long long pack2(float x, float y) {
    unsigned long long r;
    asm("mov.b64 %0, {%1, %2};" : "=l"(r) : "f"(x), "f"(y));
    return r;
}
__device__ __forceinline__ void fma2(unsigned long long& d,
                                     unsigned long long a,
                                     unsigned long long b) {
    asm("fma.rn.f32x2 %0, %1, %2, %0;" : "+l"(d) : "l"(a), "l"(b));
}

// ---------------------------------------------------------------------------
// Kernel 1: connection-weighted aggregation.
// ---------------------------------------------------------------------------
__global__ __launch_bounds__(256) void agg_kernel(
    const float* __restrict__ h,
    const float* __restrict__ w_conn,
    const int*   __restrict__ conn)
{
    extern __shared__ float smf[];
    float4* h_sm = reinterpret_cast<float4*>(smf);   // [256][16] float4

    int bn = blockIdx.x;
    int n  = bn & (NC - 1);

    const float4* hg = reinterpret_cast<const float4*>(h) + (size_t)bn * CN * DN / 4;
    for (int i = threadIdx.x; i < CN * DN / 4; i += 256) h_sm[i] = hg[i];
    __syncthreads();

    int dq = threadIdx.x & 3;
    int cr = threadIdx.x >> 2;

    for (int cp = 0; cp < 4; cp++) {
        int c = cp * 64 + cr;
        float4 a0 = {0,0,0,0}, a1 = {0,0,0,0}, a2 = {0,0,0,0}, a3 = {0,0,0,0};
        const int*   ci = conn   + ((size_t)n  * CN + c) * K;
        const float* wc = w_conn + ((size_t)bn * CN + c) * K;
        #pragma unroll
        for (int k = 0; k < K; k++) {
            int   idx = ci[k];
            float w   = wc[k];
            const float4* row = h_sm + idx * (DN / 4) + dq * 4;
            float4 r0 = row[0], r1 = row[1], r2 = row[2], r3 = row[3];
            a0.x += w * r0.x; a0.y += w * r0.y; a0.z += w * r0.z; a0.w += w * r0.w;
            a1.x += w * r1.x; a1.y += w * r1.y; a1.z += w * r1.z; a1.w += w * r1.w;
            a2.x += w * r2.x; a2.y += w * r2.y; a2.z += w * r2.z; a2.w += w * r2.w;
            a3.x += w * r3.x; a3.y += w * r3.y; a3.z += w * r3.z; a3.w += w * r3.w;
        }
        float4* out = reinterpret_cast<float4*>(g_agg + ((size_t)bn * CN + c) * DN) + dq * 4;
        out[0] = a0; out[1] = a1; out[2] = a2; out[3] = a3;
    }
}

// ---------------------------------------------------------------------------
// Kernel 2/4: grouped MLP layer 1 (feat[256][192] @ W1[128][192]^T, gelu).
// FFMA2 microtile: 8c x 8j per thread, c paired (c = tc*2 + 64u, +1).
// k-tile = 64 (exactly one feature source per tile; 3 tiles).
// ---------------------------------------------------------------------------
template<int MODE>
__global__ __launch_bounds__(512, 1) void mlp1_kernel(
    const float* __restrict__ h,
    const float* __restrict__ s1,     // MODE 1: msg; MODE 0: unused (g_agg)
    const float* __restrict__ s2,     // MODE 0: neuron_id; MODE 1: cell_context
    const float* __restrict__ w1,     // [G][HM][F]
    const float* __restrict__ b1,     // [G][HM]
    const int*   __restrict__ c2g)
{
    extern __shared__ float sm[];
    float* A  = sm;                   // [64][AP]
    float* W  = sm + 64 * AP;         // [HM*F]
    float* Bs = W + HM * F;           // [HM]

    int bn  = blockIdx.x;
    int n   = bn & (NC - 1);
    int g   = c2g[n];
    int tid = threadIdx.x;

    // Stage W1[g], b1[g]
    {
        const float4* wsrc = reinterpret_cast<const float4*>(w1 + (size_t)g * HM * F);
        float4*       wdst = reinterpret_cast<float4*>(W);
        for (int i = tid; i < HM * F / 4; i += 512) wdst[i] = wsrc[i];
        if (tid < HM) Bs[tid] = b1[g * HM + tid];
    }

    int tc = tid & 31, tj = tid >> 5;      // 16 warps -> j0 covers 128
    int cbase = tc * 2, j0 = tj * 8;

    unsigned long long acc[4][8];
    #pragma unroll
    for (int u = 0; u < 4; u++)
        #pragma unroll
        for (int j = 0; j < 8; j++) acc[u][j] = 0ULL;

    int fq   = tid & 15;    // float4 index in 64-wide f row
    int crow = tid >> 4;    // 0..31

    const float* base_h = h + (size_t)bn * CN * DN;
    const float* base1  = (MODE == 0) ? (g_agg + (size_t)bn * CN * DN)
                                      : (s1    + (size_t)bn * CN * DN);
    const float* base2  = (MODE == 0) ? (s2 + (size_t)n * CN * DN)
                                      : (s2 + (size_t)bn * DN);

    const float4* W4 = reinterpret_cast<const float4*>(W);

    for (int t = 0; t < 3; t++) {
        __syncthreads();   // first iter: covers W staging; later: compute(t-1) done
        const float* src = (t == 0) ? base_h : ((t == 1) ? base1 : base2);
        #pragma unroll
        for (int cp = 0; cp < 8; cp++) {
            int c = cp * 32 + crow;
            float4 v;
            if (MODE == 1 && t == 2)
                v = *reinterpret_cast<const float4*>(base2 + fq * 4);    // ctx broadcast
            else
                v = *reinterpret_cast<const float4*>(src + (size_t)c * DN + fq * 4);
            int kb = fq * 4;
            A[(kb + 0) * AP + c] = v.x;
            A[(kb + 1) * AP + c] = v.y;
            A[(kb + 2) * AP + c] = v.z;
            A[(kb + 3) * AP + c] = v.w;
        }
        __syncthreads();

        #pragma unroll 2
        for (int k4 = 0; k4 < 16; k4++) {
            // preload packed A pairs for 4 k, 4 u
            unsigned long long a_[4][4];
            #pragma unroll
            for (int q = 0; q < 4; q++) {
                const float* ar = A + (k4 * 4 + q) * AP + cbase;
                #pragma unroll
                for (int u = 0; u < 4; u++)
                    a_[q][u] = *reinterpret_cast<const unsigned long long*>(ar + 64 * u);
            }
            int wcol = (t * 64 + k4 * 4) >> 2;   // float4 col index in F/4=48
            #pragma unroll
            for (int jj = 0; jj < 8; jj++) {
                float4 w = W4[(j0 + jj) * 48 + wcol];
                unsigned long long b0 = pack2(w.x, w.x);
                unsigned long long b1v = pack2(w.y, w.y);
                unsigned long long b2 = pack2(w.z, w.z);
                unsigned long long b3 = pack2(w.w, w.w);
                #pragma unroll
                for (int u = 0; u < 4; u++) {
                    fma2(acc[u][jj], a_[0][u], b0);
                    fma2(acc[u][jj], a_[1][u], b1v);
                    fma2(acc[u][jj], a_[2][u], b2);
                    fma2(acc[u][jj], a_[3][u], b3);
                }
            }
        }
    }

    // Epilogue: + bias, gelu, store hidden rows to g_mh
    float bb[8];
    #pragma unroll
    for (int jj = 0; jj < 8; jj++) bb[jj] = Bs[j0 + jj];

    #pragma unroll
    for (int u = 0; u < 4; u++) {
        int c = cbase + 64 * u;
        float lo[8], hi[8];
        #pragma unroll
        for (int jj = 0; jj < 8; jj++) {
            float2 v = *reinterpret_cast<float2*>(&acc[u][jj]);
            lo[jj] = gelu_f(v.x + bb[jj]);
            hi[jj] = gelu_f(v.y + bb[jj]);
        }
        float* op0 = g_mh + ((size_t)bn * CN + c)     * HM + j0;
        float* op1 = g_mh + ((size_t)bn * CN + c + 1) * HM + j0;
        *reinterpret_cast<float4*>(op0)     = make_float4(lo[0], lo[1], lo[2], lo[3]);
        *reinterpret_cast<float4*>(op0 + 4) = make_float4(lo[4], lo[5], lo[6], lo[7]);
        *reinterpret_cast<float4*>(op1)     = make_float4(hi[0], hi[1], hi[2], hi[3]);
        *reinterpret_cast<float4*>(op1 + 4) = make_float4(hi[4], hi[5], hi[6], hi[7]);
    }
}

// ---------------------------------------------------------------------------
// Kernel 3/5: grouped MLP layer 2 (mh[256][128] @ W2[64][128]^T + bias).
// Single k-tile of 128; FFMA2 microtile 8c x 8j; 256 threads.
// MODE 1 adds residual h.
// ---------------------------------------------------------------------------
template<int MODE>
__global__ __launch_bounds__(256, 1) void mlp2_kernel(
    const float* __restrict__ w2,     // [G][DN][HM]
    const float* __restrict__ b2,     // [G][DN]
    const int*   __restrict__ c2g,
    const float* __restrict__ h,      // residual source (MODE 1)
    float*       __restrict__ out)
{
    extern __shared__ float sm[];
    float* A  = sm;                   // [128][AP]
    float* W  = sm + 128 * AP;        // [DN*HM]
    float* Bs = W + DN * HM;          // [DN]

    int bn  = blockIdx.x;
    int n   = bn & (NC - 1);
    int g   = c2g[n];
    int tid = threadIdx.x;

    {
        const float4* wsrc = reinterpret_cast<const float4*>(w2 + (size_t)g * DN * HM);
        float4*       wdst = reinterpret_cast<float4*>(W);
        for (int i = tid; i < DN * HM / 4; i += 256) wdst[i] = wsrc[i];
        if (tid < DN) Bs[tid] = b2[g * DN + tid];
    }

    // Stage full mh tile transposed: A[k][c], k=0..127
    {
        int fq   = tid & 31;   // float4 index in 128-wide row
        int crow = tid >> 5;   // 0..7
        const float* mh = g_mh + (size_t)bn * CN * HM;
        #pragma unroll 4
        for (int cp = 0; cp < 32; cp++) {
            int c = cp * 8 + crow;
            float4 v = *reinterpret_cast<const float4*>(mh + (size_t)c * HM + fq * 4);
            int kb = fq * 4;
            A[(kb + 0) * AP + c] = v.x;
            A[(kb + 1) * AP + c] = v.y;
            A[(kb + 2) * AP + c] = v.z;
            A[(kb + 3) * AP + c] = v.w;
        }
    }
    __syncthreads();

    int tc = tid & 31, tj = tid >> 5;   // 8 warps -> j0 covers 64
    int cbase = tc * 2, j0 = tj * 8;

    unsigned long long acc[4][8];
    #pragma unroll
    for (int u = 0; u < 4; u++)
        #pragma unroll
        for (int j = 0; j < 8; j++) acc[u][j] = 0ULL;

    const float4* W4 = reinterpret_cast<const float4*>(W);

    #pragma unroll 2
    for (int k4 = 0; k4 < 32; k4++) {
        unsigned long long a_[4][4];
        #pragma unroll
        for (int q = 0; q < 4; q++) {
            const float* ar = A + (k4 * 4 + q) * AP + cbase;
            #pragma unroll
            for (int u = 0; u < 4; u++)
                a_[q][u] = *reinterpret_cast<const unsigned long long*>(ar + 64 * u);
        }
        #pragma unroll
        for (int jj = 0; jj < 8; jj++) {
            float4 w = W4[(j0 + jj) * 32 + k4];
            unsigned long long b0 = pack2(w.x, w.x);
            unsigned long long b1v = pack2(w.y, w.y);
            unsigned long long b2 = pack2(w.z, w.z);
            unsigned long long b3 = pack2(w.w, w.w);
            #pragma unroll
            for (int u = 0; u < 4; u++) {
                fma2(acc[u][jj], a_[0][u], b0);
                fma2(acc[u][jj], a_[1][u], b1v);
                fma2(acc[u][jj], a_[2][u], b2);
                fma2(acc[u][jj], a_[3][u], b3);
            }
        }
    }

    float bb[8];
    #pragma unroll
    for (int jj = 0; jj < 8; jj++) bb[jj] = Bs[j0 + jj];

    #pragma unroll
    for (int u = 0; u < 4; u++) {
        int c = cbase + 64 * u;
        float lo[8], hi[8];
        #pragma unroll
        for (int jj = 0; jj < 8; jj++) {
            float2 v = *reinterpret_cast<float2*>(&acc[u][jj]);
            lo[jj] = v.x + bb[jj];
            hi[jj] = v.y + bb[jj];
        }
        if (MODE == 1) {
            const float* hp0 = h + ((size_t)bn * CN + c)     * DN + j0;
            const float* hp1 = h + ((size_t)bn * CN + c + 1) * DN + j0;
            #pragma unroll
            for (int jj = 0; jj < 8; jj++) { lo[jj] += hp0[jj]; hi[jj] += hp1[jj]; }
        }
        float* op0 = out + ((size_t)bn * CN + c)     * DN + j0;
        float* op1 = out + ((size_t)bn * CN + c + 1) * DN + j0;
        *reinterpret_cast<float4*>(op0)     = make_float4(lo[0], lo[1], lo[2], lo[3]);
        *reinterpret_cast<float4*>(op0 + 4) = make_float4(lo[4], lo[5], lo[6], lo[7]);
        *reinterpret_cast<float4*>(op1)     = make_float4(hi[0], hi[1], hi[2], hi[3]);
        *reinterpret_cast<float4*>(op1 + 4) = make_float4(hi[4], hi[5], hi[6], hi[7]);
    }
}

// ---------------------------------------------------------------------------
// Kernel 6: per-cell modulation MLP on pooled stats (coalesced pooling).
// ---------------------------------------------------------------------------
__global__ __launch_bounds__(256) void mod_kernel(
    const float* __restrict__ hnew,
    const float* __restrict__ msg,
    const float* __restrict__ mw1,    // [NC][2DN][HMOD]
    const float* __restrict__ mb1,
    const float* __restrict__ mw2,    // [NC][HMOD][MOD_OUT]
    const float* __restrict__ mb2,
    float*       __restrict__ mod)
{
    __shared__ float part[8][DN];      // [src*4 + cgroup][d]
    __shared__ float pooled[2 * DN];
    __shared__ float ph[HMOD];

    int bn  = blockIdx.x;
    int n   = bn & (NC - 1);
    int tid = threadIdx.x;

    int d  = tid & 63;
    int cg = tid >> 6;                 // 0..3
    {
        const float* p1 = hnew + (size_t)bn * CN * DN + (size_t)cg * 64 * DN + d;
        const float* p2 = msg  + (size_t)bn * CN * DN + (size_t)cg * 64 * DN + d;
        float s1 = 0.0f, s2 = 0.0f;
        #pragma unroll 8
        for (int i = 0; i < 64; i++) {
            s1 += p1[(size_t)i * DN];
            s2 += p2[(size_t)i * DN];
        }
        part[cg][d]     = s1;
        part[4 + cg][d] = s2;
    }
    __syncthreads();

    if (tid < 2 * DN) {
        int base = (tid < DN) ? 0 : 4;
        int dd   = tid & 63;
        pooled[tid] = (part[base][dd] + part[base + 1][dd] +
                       part[base + 2][dd] + part[base + 3][dd]) * (1.0f / CN);
    }
    __syncthreads();

    if (tid < HMOD) {
        const float* w = mw1 + (size_t)n * (2 * DN) * HMOD + tid;
        float acc = mb1[n * HMOD + tid];
        #pragma unroll 8
        for (int f = 0; f < 2 * DN; f++) acc = fmaf(pooled[f], w[f * HMOD], acc);
        ph[tid] = gelu_f(acc);
    }
    __syncthreads();

    if (tid < MOD_OUT) {
        const float* w = mw2 + (size_t)n * HMOD * MOD_OUT + tid;
        float acc = mb2[n * MOD_OUT + tid];
        #pragma unroll 8
        for (int k = 0; k < HMOD; k++) acc = fmaf(ph[k], w[k * MOD_OUT], acc);
        mod[bn * MOD_OUT + tid] = acc;
    }
}

// ---------------------------------------------------------------------------
// Launch
// ---------------------------------------------------------------------------
extern "C" void kernel_launch(void* const* d_in, const int* in_sizes, int n_in,
                              void* d_out, int out_size)
{
    const float* h      = (const float*)d_in[0];
    const float* w_conn = (const float*)d_in[1];
    const float* ctx    = (const float*)d_in[2];
    const float* nid    = (const float*)d_in[3];
    const float* mw1    = (const float*)d_in[4];
    const float* mb1    = (const float*)d_in[5];
    const float* mw2    = (const float*)d_in[6];
    const float* mb2    = (const float*)d_in[7];
    const float* sw1    = (const float*)d_in[8];
    const float* sb1    = (const float*)d_in[9];
    const float* sw2    = (const float*)d_in[10];
    const float* sb2    = (const float*)d_in[11];
    const float* modw1  = (const float*)d_in[12];
    const float* modb1  = (const float*)d_in[13];
    const float* modw2  = (const float*)d_in[14];
    const float* modb2  = (const float*)d_in[15];
    const int*   conn   = (const int*)d_in[16];
    const int*   c2g    = (const int*)d_in[17];

    float* out   = (float*)d_out;
    float* o_h   = out;
    float* o_msg = out + (size_t)Bb * NC * CN * DN;
    float* o_mod = o_msg + (size_t)Bb * NC * CN * DN;

    const int grid = Bb * NC;  // 512

    const size_t smA = (size_t)CN * DN * sizeof(float);                     // 64 KB
    const size_t sm1 = (size_t)(64 * AP + HM * F + HM) * sizeof(float);     // ~161 KB
    const size_t sm2 = (size_t)(128 * AP + DN * HM + DN) * sizeof(float);   // ~161 KB

    static bool attr_done = false;
    if (!attr_done) {
        cudaFuncSetAttribute(agg_kernel,     cudaFuncAttributeMaxDynamicSharedMemorySize, (int)smA);
        cudaFuncSetAttribute(mlp1_kernel<0>, cudaFuncAttributeMaxDynamicSharedMemorySize, (int)sm1);
        cudaFuncSetAttribute(mlp1_kernel<1>, cudaFuncAttributeMaxDynamicSharedMemorySize, (int)sm1);
        cudaFuncSetAttribute(mlp2_kernel<0>, cudaFuncAttributeMaxDynamicSharedMemorySize, (int)sm2);
        cudaFuncSetAttribute(mlp2_kernel<1>, cudaFuncAttributeMaxDynamicSharedMemorySize, (int)sm2);
        attr_done = true;
    }

    agg_kernel<<<grid, 256, smA>>>(h, w_conn, conn);
    mlp1_kernel<0><<<grid, 512, sm1>>>(h, nullptr, nid, mw1, mb1, c2g);
    mlp2_kernel<0><<<grid, 256, sm2>>>(mw2, mb2, c2g, h, o_msg);
    mlp1_kernel<1><<<grid, 512, sm1>>>(h, o_msg, ctx, sw1, sb1, c2g);
    mlp2_kernel<1><<<grid, 256, sm2>>>(sw2, sb2, c2g, h, o_h);
    mod_kernel<<<grid, 256>>>(o_h, o_msg, modw1, modb1, modw2, modb2, o_mod);
}